// round 12
// baseline (speedup 1.0000x reference)
#include <cuda_runtime.h>
#include <cuda_fp16.h>
#include <mma.h>
#include <cstdint>

using namespace nvcuda;

#define NB      256
#define NCOLS   512
#define NNODE   256
#define VOCAB   100
#define DH      128
#define NTOT    (2*NB*NNODE)      /* 131072 nodes */
#define EINT    (NTOT*8)          /* 1048576 edges */
#define MERGED  (NB*NNODE)        /* 65536 */
#define LN_EPSF 1e-5f

// ---------------- scratch (device globals; no allocation allowed) -----------
__device__ __half g_h[(size_t)NTOT * DH];   // node features (fp16)
__device__ __half g_z[(size_t)NTOT * DH];   // (1+eps)*h + agg (fp16)
__device__ float  g_tab[2][38 * DH];        // los_table @ ew + eb (per layer)
__device__ __half g_wh[8][DH * DH];         // fp16-converted weights
__device__ int    g_cnt[NTOT];
__device__ int    g_off[NTOT];
__device__ int    g_cur[NTOT];
__device__ int    g_eid[EINT];
__device__ int    g_part[512];

// ---------------- helpers ------------------------------------------------------
struct F8 { float4 a, b; };

__device__ __forceinline__ F8 u4f8(uint4 v) {
    F8 r;
    float2 p0 = __half22float2(*reinterpret_cast<__half2*>(&v.x));
    float2 p1 = __half22float2(*reinterpret_cast<__half2*>(&v.y));
    float2 p2 = __half22float2(*reinterpret_cast<__half2*>(&v.z));
    float2 p3 = __half22float2(*reinterpret_cast<__half2*>(&v.w));
    r.a = make_float4(p0.x, p0.y, p1.x, p1.y);
    r.b = make_float4(p2.x, p2.y, p3.x, p3.y);
    return r;
}
__device__ __forceinline__ uint4 f8u4(F8 v) {
    __half2 h0 = __floats2half2_rn(v.a.x, v.a.y);
    __half2 h1 = __floats2half2_rn(v.a.z, v.a.w);
    __half2 h2 = __floats2half2_rn(v.b.x, v.b.y);
    __half2 h3 = __floats2half2_rn(v.b.z, v.b.w);
    uint4 r;
    r.x = *reinterpret_cast<uint32_t*>(&h0);
    r.y = *reinterpret_cast<uint32_t*>(&h1);
    r.z = *reinterpret_cast<uint32_t*>(&h2);
    r.w = *reinterpret_cast<uint32_t*>(&h3);
    return r;
}

// ---------------- weight pre-convert to fp16 ----------------------------------
__global__ void convw_k(const float* p0, const float* p1, const float* p2,
                        const float* p3, const float* p4, const float* p5,
                        const float* p6, const float* p7) {
    int m = blockIdx.y;
    const float* p = (m == 0) ? p0 : (m == 1) ? p1 : (m == 2) ? p2 : (m == 3) ? p3
                   : (m == 4) ? p4 : (m == 5) ? p5 : (m == 6) ? p6 : p7;
    int i = blockIdx.x * 256 + threadIdx.x;
    g_wh[m][i] = __float2half_rn(__ldg(&p[i]));
}

// ---------------- embedding gather (writes fp16 h, uint4 lanes) ---------------
__global__ void embed_k(const int* __restrict__ x, const float* __restrict__ emb) {
    int tid = blockIdx.x * blockDim.x + threadIdx.x;
    int n = tid >> 4, l = tid & 15;
    if (n >= NTOT) return;
    int c = n & (NCOLS - 1);
    int b = n >> 9;
    int v = __ldg(&x[b * NCOLS + c]);
    const float4* row = reinterpret_cast<const float4*>(emb + ((size_t)c * VOCAB + v) * DH);
    F8 f;
    f.a = __ldg(row + 2 * l);
    f.b = __ldg(row + 2 * l + 1);
    reinterpret_cast<uint4*>(g_h)[(size_t)n * 16 + l] = f8u4(f);
}

// ---------------- CSR build ---------------------------------------------------
__global__ void hist_k(const int* __restrict__ dst) {
    int e = blockIdx.x * 256 + threadIdx.x;
    if (e < EINT) atomicAdd(&g_cnt[__ldg(&dst[e])], 1);
}

__global__ void scanA_k() {
    __shared__ int s[256];
    int t = threadIdx.x;
    int i = blockIdx.x * 256 + t;
    int c = g_cnt[i];
    s[t] = c;
    __syncthreads();
#pragma unroll
    for (int o = 1; o < 256; o <<= 1) {
        int v = (t >= o) ? s[t - o] : 0;
        __syncthreads();
        s[t] += v;
        __syncthreads();
    }
    g_off[i] = s[t];
    if (t == 255) g_part[blockIdx.x] = s[255];
}

__global__ void scanB_k() {
    __shared__ int s[512];
    int t = threadIdx.x;
    int c = g_part[t];
    s[t] = c;
    __syncthreads();
#pragma unroll
    for (int o = 1; o < 512; o <<= 1) {
        int v = (t >= o) ? s[t - o] : 0;
        __syncthreads();
        s[t] += v;
        __syncthreads();
    }
    g_part[t] = s[t] - c;
}

__global__ void scanC_k() {
    int i = blockIdx.x * 256 + threadIdx.x;
    int off = g_off[i] - g_cnt[i] + g_part[blockIdx.x];
    g_off[i] = off;
    g_cur[i] = off;
}

__global__ void fill_k(const int* __restrict__ src, const int* __restrict__ dst) {
    int e = blockIdx.x * 256 + threadIdx.x;
    if (e >= EINT) return;
    int d = __ldg(&dst[e]);
    int p = atomicAdd(&g_cur[d], 1);
    g_eid[p] = __ldg(&src[e]);
}

// ---------------- GIN aggregation: 2 nodes/warp, 16 lanes x uint4 -------------
__global__ void agg1_k(const float* __restrict__ epsp) {
    int wid = threadIdx.x >> 5, lane = threadIdx.x & 31;
    int half = lane >> 4, l = lane & 15;
    int n = blockIdx.x * 16 + wid * 2 + half;
    float s = 1.0f + __ldg(epsp);
    const uint4* h4 = reinterpret_cast<const uint4*>(g_h);
    F8 a = u4f8(h4[(size_t)n * 16 + l]);
    F8 acc;
    acc.a = make_float4(a.a.x * s, a.a.y * s, a.a.z * s, a.a.w * s);
    acc.b = make_float4(a.b.x * s, a.b.y * s, a.b.z * s, a.b.w * s);
    int off = g_off[n], deg = g_cnt[n];
    int k = 0;
    for (; k + 8 <= deg; k += 8) {
        F8 v[8];
#pragma unroll
        for (int j = 0; j < 8; j++) {
            int e = __ldg(&g_eid[off + k + j]);
            v[j] = u4f8(__ldg(&h4[(size_t)e * 16 + l]));
        }
#pragma unroll
        for (int j = 0; j < 8; j++) {
            acc.a.x += v[j].a.x; acc.a.y += v[j].a.y; acc.a.z += v[j].a.z; acc.a.w += v[j].a.w;
            acc.b.x += v[j].b.x; acc.b.y += v[j].b.y; acc.b.z += v[j].b.z; acc.b.w += v[j].b.w;
        }
    }
    for (; k < deg; k++) {
        F8 v = u4f8(__ldg(&h4[(size_t)__ldg(&g_eid[off + k]) * 16 + l]));
        acc.a.x += v.a.x; acc.a.y += v.a.y; acc.a.z += v.a.z; acc.a.w += v.a.w;
        acc.b.x += v.b.x; acc.b.y += v.b.y; acc.b.z += v.b.z; acc.b.w += v.b.w;
    }
    reinterpret_cast<uint4*>(g_z)[(size_t)n * 16 + l] = f8u4(acc);
}

// ---------------- GINE aggregation --------------------------------------------
__global__ void agg2_k(const float* __restrict__ epsp, const int* __restrict__ los,
                       const float* __restrict__ tab) {
    int wid = threadIdx.x >> 5, lane = threadIdx.x & 31;
    int half = lane >> 4, l = lane & 15;
    int n = blockIdx.x * 16 + wid * 2 + half;
    float s = 1.0f + __ldg(epsp);
    const uint4* h4 = reinterpret_cast<const uint4*>(g_h);
    const float4* t4 = reinterpret_cast<const float4*>(tab);
    float4 c0a = t4[2 * l], c0b = t4[2 * l + 1];
    F8 a = u4f8(h4[(size_t)n * 16 + l]);
    F8 acc;
    acc.a = make_float4(a.a.x * s, a.a.y * s, a.a.z * s, a.a.w * s);
    acc.b = make_float4(a.b.x * s, a.b.y * s, a.b.z * s, a.b.w * s);
    int off = g_off[n], deg = g_cnt[n];
    int k = 0;
    for (; k + 8 <= deg; k += 8) {
        F8 v[8];
#pragma unroll
        for (int j = 0; j < 8; j++) {
            int e = __ldg(&g_eid[off + k + j]);
            v[j] = u4f8(__ldg(&h4[(size_t)e * 16 + l]));
        }
#pragma unroll
        for (int j = 0; j < 8; j++) {
            acc.a.x += fmaxf(v[j].a.x + c0a.x, 0.f);
            acc.a.y += fmaxf(v[j].a.y + c0a.y, 0.f);
            acc.a.z += fmaxf(v[j].a.z + c0a.z, 0.f);
            acc.a.w += fmaxf(v[j].a.w + c0a.w, 0.f);
            acc.b.x += fmaxf(v[j].b.x + c0b.x, 0.f);
            acc.b.y += fmaxf(v[j].b.y + c0b.y, 0.f);
            acc.b.z += fmaxf(v[j].b.z + c0b.z, 0.f);
            acc.b.w += fmaxf(v[j].b.w + c0b.w, 0.f);
        }
    }
    for (; k < deg; k++) {
        F8 v = u4f8(__ldg(&h4[(size_t)__ldg(&g_eid[off + k]) * 16 + l]));
        acc.a.x += fmaxf(v.a.x + c0a.x, 0.f);
        acc.a.y += fmaxf(v.a.y + c0a.y, 0.f);
        acc.a.z += fmaxf(v.a.z + c0a.z, 0.f);
        acc.a.w += fmaxf(v.a.w + c0a.w, 0.f);
        acc.b.x += fmaxf(v.b.x + c0b.x, 0.f);
        acc.b.y += fmaxf(v.b.y + c0b.y, 0.f);
        acc.b.z += fmaxf(v.b.z + c0b.z, 0.f);
        acc.b.w += fmaxf(v.b.w + c0b.w, 0.f);
    }
    if (n >= MERGED) {
        int m = n - MERGED;
        int lo = __ldg(&los[m >> 8]);
        float4 ta = t4[lo * 32 + 2 * l], tb = t4[lo * 32 + 2 * l + 1];
        F8 v = u4f8(h4[(size_t)m * 16 + l]);
        acc.a.x += fmaxf(v.a.x + ta.x, 0.f);
        acc.a.y += fmaxf(v.a.y + ta.y, 0.f);
        acc.a.z += fmaxf(v.a.z + ta.z, 0.f);
        acc.a.w += fmaxf(v.a.w + ta.w, 0.f);
        acc.b.x += fmaxf(v.b.x + tb.x, 0.f);
        acc.b.y += fmaxf(v.b.y + tb.y, 0.f);
        acc.b.z += fmaxf(v.b.z + tb.z, 0.f);
        acc.b.w += fmaxf(v.b.w + tb.w, 0.f);
    }
    reinterpret_cast<uint4*>(g_z)[(size_t)n * 16 + l] = f8u4(acc);
}

// ---------------- tab[r][:] = los_table[r] @ ew + eb --------------------------
__global__ void table_k(const float* __restrict__ lt, const float* __restrict__ ew,
                        const float* __restrict__ eb, float* __restrict__ tab) {
    int r = blockIdx.x, d = threadIdx.x;
    float acc = __ldg(&eb[d]);
#pragma unroll
    for (int j = 0; j < 8; j++)
        acc += __ldg(&lt[r * 8 + j]) * __ldg(&ew[j * DH + d]);
    tab[r * DH + d] = acc;
}

// ---------------- fused MLP, fp16 HMMA (m16n16k16) -----------------------------
// smem: [As | W1s | W2s | params], all halves 128x136; W2 preloaded upfront.
// fp32 inter (128x132) overlays As+W1s (dead after GEMM1); W2s preserved.
#define HS 136            /* half stride */
#define IS 132            /* float inter stride */
#define AS_BYTES (128*HS*2)          /* 34816 */
#define W1_OFF  AS_BYTES
#define W2_OFF  (2*AS_BYTES)
#define PRM_OFF (3*AS_BYTES)         /* 104448 */
#define MLP_SMEM_BYTES (PRM_OFF + 6*128*4)   /* 107520 */

__device__ __forceinline__ void do_gemm_h(
    const __half* __restrict__ A, const __half* __restrict__ B,
    wmma::fragment<wmma::accumulator, 16, 16, 16, float> (&acc)[8], int wrow)
{
#pragma unroll
    for (int k = 0; k < 8; k++) {
        wmma::fragment<wmma::matrix_a, 16, 16, 16, __half, wmma::row_major> a;
        wmma::load_matrix_sync(a, A + wrow * 16 * HS + k * 16, HS);
#pragma unroll
        for (int j = 0; j < 8; j++) {
            wmma::fragment<wmma::matrix_b, 16, 16, 16, __half, wmma::row_major> b;
            wmma::load_matrix_sync(b, B + k * 16 * HS + j * 16, HS);
            wmma::mma_sync(acc[j], a, b, acc[j]);
        }
    }
}

__global__ __launch_bounds__(256, 2) void mlp_k(
    const __half* __restrict__ A, const __half* __restrict__ W1,
    const float* __restrict__ b1, const float* __restrict__ gam,
    const float* __restrict__ bet, const __half* __restrict__ W2,
    const float* __restrict__ b2, __half* __restrict__ Out)
{
    extern __shared__ char smc[];
    __half* As    = reinterpret_cast<__half*>(smc);
    __half* W1s   = reinterpret_cast<__half*>(smc + W1_OFF);
    __half* W2s   = reinterpret_cast<__half*>(smc + W2_OFF);
    float*  inter = reinterpret_cast<float*>(smc);          // overlays As+W1s
    float*  bs    = reinterpret_cast<float*>(smc + PRM_OFF);
    float*  gs    = bs + 128;
    float*  bes   = gs + 128;
    float*  b2s   = bes + 128;
    float*  mus   = b2s + 128;
    float*  invs  = mus + 128;

    int tid = threadIdx.x;
    int wid = tid >> 5;
    size_t n0 = (size_t)blockIdx.x * 128;

    if (tid < 128) {
        bs[tid]  = __ldg(&b1[tid]);
        gs[tid]  = __ldg(&gam[tid]);
        bes[tid] = __ldg(&bet[tid]);
        b2s[tid] = __ldg(&b2[tid]);
    }

    // load A tile + BOTH weight matrices up front
    {
        const uint4* ap  = reinterpret_cast<const uint4*>(A + n0 * DH);
        const uint4* w1p = reinterpret_cast<const uint4*>(W1);
        const uint4* w2p = reinterpret_cast<const uint4*>(W2);
#pragma unroll
        for (int it = 0; it < 8; it++) {
            int i = tid + it * 256;          // 0..2047
            int r = i >> 4, c8 = (i & 15) * 8;
            *reinterpret_cast<uint4*>(As  + r * HS + c8) = __ldg(ap  + i);
            *reinterpret_cast<uint4*>(W1s + r * HS + c8) = __ldg(w1p + i);
            *reinterpret_cast<uint4*>(W2s + r * HS + c8) = __ldg(w2p + i);
        }
    }
    __syncthreads();

    wmma::fragment<wmma::accumulator, 16, 16, 16, float> acc[8];
#pragma unroll
    for (int j = 0; j < 8; j++) wmma::fill_fragment(acc[j], 0.0f);

    do_gemm_h(As, W1s, acc, wid);
    __syncthreads();                          // all reads of As/W1s done

    // store GEMM1 result to fp32 inter (overlays As+W1s; W2s untouched)
#pragma unroll
    for (int j = 0; j < 8; j++)
        wmma::store_matrix_sync(inter + wid * 16 * IS + j * 16, acc[j], IS, wmma::mem_row_major);
    __syncthreads();

    // LN stats: 2 threads per row
    {
        int row = tid >> 1, hf = tid & 1;
        const float* rp = inter + row * IS + hf * 64;
        const float* bp = bs + hf * 64;
        float s = 0.f, ss = 0.f;
#pragma unroll
        for (int c = 0; c < 64; c++) {
            float xv = rp[c] + bp[c];
            s += xv; ss += xv * xv;
        }
        s  += __shfl_xor_sync(0xffffffffu, s, 1);
        ss += __shfl_xor_sync(0xffffffffu, ss, 1);
        if (hf == 0) {
            float mu = s * (1.0f / 128.0f);
            float var = ss * (1.0f / 128.0f) - mu * mu;
            mus[row] = mu;
            invs[row] = rsqrtf(var + LN_EPSF);
        }
    }
    __syncthreads();

    // apply LN+relu: inter -> regs (half2 packed), then write As
    uint32_t pk[32];
#pragma unroll
    for (int it = 0; it < 32; it++) {
        int i = tid + it * 256;              // 0..8191 (half2 index)
        int r = i >> 6, c2 = i & 63;
        float mu = mus[r], inv = invs[r];
        float x0 = inter[r * IS + 2 * c2]     + bs[2 * c2];
        float x1 = inter[r * IS + 2 * c2 + 1] + bs[2 * c2 + 1];
        float y0 = fmaxf((x0 - mu) * inv * gs[2 * c2]     + bes[2 * c2],     0.f);
        float y1 = fmaxf((x1 - mu) * inv * gs[2 * c2 + 1] + bes[2 * c2 + 1], 0.f);
        __half2 h = __floats2half2_rn(y0, y1);
        pk[it] = *reinterpret_cast<uint32_t*>(&h);
    }
    __syncthreads();                          // all inter reads done
    {
        uint32_t* asu = reinterpret_cast<uint32_t*>(As);
#pragma unroll
        for (int it = 0; it < 32; it++) {
            int i = tid + it * 256;
            int r = i >> 6, c2 = i & 63;
            asu[r * (HS / 2) + c2] = pk[it];
        }
    }
    __syncthreads();

#pragma unroll
    for (int j = 0; j < 8; j++) wmma::fill_fragment(acc[j], 0.0f);

    do_gemm_h(As, W2s, acc, wid);
    __syncthreads();

#pragma unroll
    for (int j = 0; j < 8; j++)
        wmma::store_matrix_sync(inter + wid * 16 * IS + j * 16, acc[j], IS, wmma::mem_row_major);
    __syncthreads();

    // epilogue: + b2, convert to half, write global
    {
        uint32_t* op = reinterpret_cast<uint32_t*>(Out + n0 * DH);
#pragma unroll
        for (int it = 0; it < 32; it++) {
            int i = tid + it * 256;
            int r = i >> 6, c2 = i & 63;
            float x0 = inter[r * IS + 2 * c2]     + b2s[2 * c2];
            float x1 = inter[r * IS + 2 * c2 + 1] + b2s[2 * c2 + 1];
            __half2 h = __floats2half2_rn(x0, x1);
            op[i] = *reinterpret_cast<uint32_t*>(&h);
        }
    }
}

// ---------------- per-graph node sum (half in, float out) ----------------------
__global__ void sum_k(float* __restrict__ out, int off) {
    int g = blockIdx.x, d = threadIdx.x;    // 64 threads, d = half2 col index
    const uint32_t* base = reinterpret_cast<const uint32_t*>(g_h) + (size_t)g * NNODE * 64 + d;
    float sx = 0.f, sy = 0.f;
#pragma unroll 8
    for (int j = 0; j < NNODE; j++) {
        uint32_t v = base[(size_t)j * 64];
        float2 f = __half22float2(*reinterpret_cast<const __half2*>(&v));
        sx += f.x; sy += f.y;
    }
    out[g * 256 + off + 2 * d]     = sx;
    out[g * 256 + off + 2 * d + 1] = sy;
}

// ---------------- launch ------------------------------------------------------
extern "C" void kernel_launch(void* const* d_in, const int* in_sizes, int n_in,
                              void* d_out, int out_size)
{
    const int*   x     = (const int*)d_in[0];
    const int*   ei    = (const int*)d_in[1];
    const int*   los   = (const int*)d_in[2];
    const float* emb   = (const float*)d_in[3];
    const float* lt    = (const float*)d_in[4];
    const float* g1w1  = (const float*)d_in[5];
    const float* g1b1  = (const float*)d_in[6];
    const float* g1g   = (const float*)d_in[7];
    const float* g1be  = (const float*)d_in[8];
    const float* g1w2  = (const float*)d_in[9];
    const float* g1b2  = (const float*)d_in[10];
    const float* g1eps = (const float*)d_in[11];
    const float* g2w1  = (const float*)d_in[12];
    const float* g2b1  = (const float*)d_in[13];
    const float* g2g   = (const float*)d_in[14];
    const float* g2be  = (const float*)d_in[15];
    const float* g2w2  = (const float*)d_in[16];
    const float* g2b2  = (const float*)d_in[17];
    const float* g2eps = (const float*)d_in[18];
    const float* g2ew  = (const float*)d_in[19];
    const float* g2eb  = (const float*)d_in[20];
    float* out = (float*)d_out;

    const int* src = ei;
    const int* dst = ei + EINT;

    void *ph, *pz, *pc, *pw, *pt;
    cudaGetSymbolAddress(&ph, g_h);
    cudaGetSymbolAddress(&pz, g_z);
    cudaGetSymbolAddress(&pc, g_cnt);
    cudaGetSymbolAddress(&pw, g_wh);
    cudaGetSymbolAddress(&pt, g_tab);
    __half* hB = (__half*)ph;
    __half* zB = (__half*)pz;
    __half* wB = (__half*)pw;
    float*  tB = (float*)pt;

    static int smem_set = 0;
    if (!smem_set) {
        cudaFuncSetAttribute(mlp_k, cudaFuncAttributeMaxDynamicSharedMemorySize,
                             MLP_SMEM_BYTES);
        smem_set = 1;
    }

    // weights: [g1w1L0, g1w2L0, g1w1L1, g1w2L1, g2w1L0, g2w2L0, g2w1L1, g2w2L1]
    convw_k<<<dim3(64, 8), 256>>>(
        g1w1, g1w2, g1w1 + DH * DH, g1w2 + DH * DH,
        g2w1, g2w2, g2w1 + DH * DH, g2w2 + DH * DH);

    // edge-attr tables for both GINE layers (hoisted off the round path)
    table_k<<<38, DH>>>(lt, g2ew, g2eb, tB);
    table_k<<<38, DH>>>(lt, g2ew + (size_t)8 * DH, g2eb + DH, tB + 38 * DH);

    embed_k<<<(NTOT * 16) / 256, 256>>>(x, emb);

    // CSR build
    cudaMemsetAsync(pc, 0, NTOT * sizeof(int));
    hist_k<<<EINT / 256, 256>>>(dst);
    scanA_k<<<NTOT / 256, 256>>>();
    scanB_k<<<1, 512>>>();
    scanC_k<<<NTOT / 256, 256>>>();
    fill_k<<<EINT / 256, 256>>>(src, dst);

    // ---- GIN layer group 1 ----
    for (int i = 0; i < 2; i++) {
        agg1_k<<<NTOT / 16, 256>>>(g1eps + i);
        mlp_k<<<NTOT / 128, 256, MLP_SMEM_BYTES>>>(
            zB, wB + (size_t)(2 * i) * DH * DH, g1b1 + i * DH, g1g + i * DH,
            g1be + i * DH, wB + (size_t)(2 * i + 1) * DH * DH, g1b2 + i * DH, hB);
    }
    sum_k<<<2 * NB, 64>>>(out, 0);

    // ---- GINE layer group 2 ----
    for (int i = 0; i < 2; i++) {
        agg2_k<<<NTOT / 16, 256>>>(g2eps + i, los, tB + (size_t)i * 38 * DH);
        mlp_k<<<NTOT / 128, 256, MLP_SMEM_BYTES>>>(
            zB, wB + (size_t)(4 + 2 * i) * DH * DH, g2b1 + i * DH, g2g + i * DH,
            g2be + i * DH, wB + (size_t)(5 + 2 * i) * DH * DH, g2b2 + i * DH, hB);
    }
    sum_k<<<2 * NB, 64>>>(out, 128);
}

// round 13
// speedup vs baseline: 1.0387x; 1.0387x over previous
#include <cuda_runtime.h>
#include <cuda_fp16.h>
#include <mma.h>
#include <cstdint>

using namespace nvcuda;

#define NB      256
#define NCOLS   512
#define NNODE   256
#define VOCAB   100
#define DH      128
#define NTOT    (2*NB*NNODE)      /* 131072 nodes */
#define EINT    (NTOT*8)          /* 1048576 edges */
#define MERGED  (NB*NNODE)        /* 65536 */
#define LN_EPSF 1e-5f

// ---------------- scratch (device globals; no allocation allowed) -----------
__device__ __half g_h[(size_t)NTOT * DH];   // node features (fp16)
__device__ __half g_z[(size_t)NTOT * DH];   // (1+eps)*h + agg (fp16)
__device__ float  g_tab[2][38 * DH];        // los_table @ ew + eb (per layer)
__device__ __half g_wh[8][DH * DH];         // fp16-converted weights
__device__ int    g_cnt[NTOT];
__device__ int    g_off[NTOT];
__device__ int    g_cur[NTOT];
__device__ int    g_eid[EINT];
__device__ int    g_part[512];

// ---------------- helpers ------------------------------------------------------
struct F8 { float4 a, b; };

__device__ __forceinline__ float4 h4f(uint2 v) {
    float2 a = __half22float2(*reinterpret_cast<__half2*>(&v.x));
    float2 b = __half22float2(*reinterpret_cast<__half2*>(&v.y));
    return make_float4(a.x, a.y, b.x, b.y);
}
__device__ __forceinline__ uint2 f4h(float4 v) {
    __half2 a = __floats2half2_rn(v.x, v.y);
    __half2 b = __floats2half2_rn(v.z, v.w);
    uint2 r;
    r.x = *reinterpret_cast<uint32_t*>(&a);
    r.y = *reinterpret_cast<uint32_t*>(&b);
    return r;
}
__device__ __forceinline__ uint4 f8u4(F8 v) {
    __half2 h0 = __floats2half2_rn(v.a.x, v.a.y);
    __half2 h1 = __floats2half2_rn(v.a.z, v.a.w);
    __half2 h2 = __floats2half2_rn(v.b.x, v.b.y);
    __half2 h3 = __floats2half2_rn(v.b.z, v.b.w);
    uint4 r;
    r.x = *reinterpret_cast<uint32_t*>(&h0);
    r.y = *reinterpret_cast<uint32_t*>(&h1);
    r.z = *reinterpret_cast<uint32_t*>(&h2);
    r.w = *reinterpret_cast<uint32_t*>(&h3);
    return r;
}

// ---------------- weight pre-convert to fp16 ----------------------------------
__global__ void convw_k(const float* p0, const float* p1, const float* p2,
                        const float* p3, const float* p4, const float* p5,
                        const float* p6, const float* p7) {
    int m = blockIdx.y;
    const float* p = (m == 0) ? p0 : (m == 1) ? p1 : (m == 2) ? p2 : (m == 3) ? p3
                   : (m == 4) ? p4 : (m == 5) ? p5 : (m == 6) ? p6 : p7;
    int i = blockIdx.x * 256 + threadIdx.x;
    g_wh[m][i] = __float2half_rn(__ldg(&p[i]));
}

// ---------------- embedding gather (writes fp16 h, uint4 lanes) ---------------
__global__ void embed_k(const int* __restrict__ x, const float* __restrict__ emb) {
    int tid = blockIdx.x * blockDim.x + threadIdx.x;
    int n = tid >> 4, l = tid & 15;
    if (n >= NTOT) return;
    int c = n & (NCOLS - 1);
    int b = n >> 9;
    int v = __ldg(&x[b * NCOLS + c]);
    const float4* row = reinterpret_cast<const float4*>(emb + ((size_t)c * VOCAB + v) * DH);
    F8 f;
    f.a = __ldg(row + 2 * l);
    f.b = __ldg(row + 2 * l + 1);
    reinterpret_cast<uint4*>(g_h)[(size_t)n * 16 + l] = f8u4(f);
}

// ---------------- CSR build ---------------------------------------------------
__global__ void hist_k(const int* __restrict__ dst) {
    int e = blockIdx.x * 256 + threadIdx.x;
    if (e < EINT) atomicAdd(&g_cnt[__ldg(&dst[e])], 1);
}

__global__ void scanA_k() {
    __shared__ int s[256];
    int t = threadIdx.x;
    int i = blockIdx.x * 256 + t;
    int c = g_cnt[i];
    s[t] = c;
    __syncthreads();
#pragma unroll
    for (int o = 1; o < 256; o <<= 1) {
        int v = (t >= o) ? s[t - o] : 0;
        __syncthreads();
        s[t] += v;
        __syncthreads();
    }
    g_off[i] = s[t];
    if (t == 255) g_part[blockIdx.x] = s[255];
}

__global__ void scanB_k() {
    __shared__ int s[512];
    int t = threadIdx.x;
    int c = g_part[t];
    s[t] = c;
    __syncthreads();
#pragma unroll
    for (int o = 1; o < 512; o <<= 1) {
        int v = (t >= o) ? s[t - o] : 0;
        __syncthreads();
        s[t] += v;
        __syncthreads();
    }
    g_part[t] = s[t] - c;
}

__global__ void scanC_k() {
    int i = blockIdx.x * 256 + threadIdx.x;
    int off = g_off[i] - g_cnt[i] + g_part[blockIdx.x];
    g_off[i] = off;
    g_cur[i] = off;
}

__global__ void fill_k(const int* __restrict__ src, const int* __restrict__ dst) {
    int e = blockIdx.x * 256 + threadIdx.x;
    if (e >= EINT) return;
    int d = __ldg(&dst[e]);
    int p = atomicAdd(&g_cur[d], 1);
    g_eid[p] = __ldg(&src[e]);
}

// ---------------- GIN aggregation (1 node/warp, uint2 lanes, 8-unroll) --------
__global__ void agg1_k(const float* __restrict__ epsp) {
    int tid = blockIdx.x * 256 + threadIdx.x;
    int n = tid >> 5, l = tid & 31;
    float s = 1.0f + __ldg(epsp);
    const uint2* h2 = reinterpret_cast<const uint2*>(g_h);
    float4 a = h4f(h2[(size_t)n * 32 + l]);
    float4 acc = make_float4(a.x * s, a.y * s, a.z * s, a.w * s);
    int off = g_off[n], deg = g_cnt[n];
    int k = 0;
    for (; k + 8 <= deg; k += 8) {
        float4 v[8];
#pragma unroll
        for (int j = 0; j < 8; j++) {
            int e = __ldg(&g_eid[off + k + j]);
            v[j] = h4f(__ldg(&h2[(size_t)e * 32 + l]));
        }
#pragma unroll
        for (int j = 0; j < 8; j++) {
            acc.x += v[j].x; acc.y += v[j].y; acc.z += v[j].z; acc.w += v[j].w;
        }
    }
    for (; k < deg; k++) {
        float4 v = h4f(__ldg(&h2[(size_t)__ldg(&g_eid[off + k]) * 32 + l]));
        acc.x += v.x; acc.y += v.y; acc.z += v.z; acc.w += v.w;
    }
    reinterpret_cast<uint2*>(g_z)[(size_t)n * 32 + l] = f4h(acc);
}

// ---------------- GINE aggregation --------------------------------------------
__global__ void agg2_k(const float* __restrict__ epsp, const int* __restrict__ los,
                       const float* __restrict__ tab) {
    int tid = blockIdx.x * 256 + threadIdx.x;
    int n = tid >> 5, l = tid & 31;
    float s = 1.0f + __ldg(epsp);
    const uint2* h2 = reinterpret_cast<const uint2*>(g_h);
    const float4* t4 = reinterpret_cast<const float4*>(tab);
    float4 c0 = t4[l];
    float4 a = h4f(h2[(size_t)n * 32 + l]);
    float4 acc = make_float4(a.x * s, a.y * s, a.z * s, a.w * s);
    int off = g_off[n], deg = g_cnt[n];
    int k = 0;
    for (; k + 8 <= deg; k += 8) {
        float4 v[8];
#pragma unroll
        for (int j = 0; j < 8; j++) {
            int e = __ldg(&g_eid[off + k + j]);
            v[j] = h4f(__ldg(&h2[(size_t)e * 32 + l]));
        }
#pragma unroll
        for (int j = 0; j < 8; j++) {
            acc.x += fmaxf(v[j].x + c0.x, 0.f);
            acc.y += fmaxf(v[j].y + c0.y, 0.f);
            acc.z += fmaxf(v[j].z + c0.z, 0.f);
            acc.w += fmaxf(v[j].w + c0.w, 0.f);
        }
    }
    for (; k < deg; k++) {
        float4 v = h4f(__ldg(&h2[(size_t)__ldg(&g_eid[off + k]) * 32 + l]));
        acc.x += fmaxf(v.x + c0.x, 0.f);
        acc.y += fmaxf(v.y + c0.y, 0.f);
        acc.z += fmaxf(v.z + c0.z, 0.f);
        acc.w += fmaxf(v.w + c0.w, 0.f);
    }
    if (n >= MERGED) {
        int m = n - MERGED;
        int lo = __ldg(&los[m >> 8]);
        float4 t = t4[lo * 32 + l];
        float4 v = h4f(h2[(size_t)m * 32 + l]);
        acc.x += fmaxf(v.x + t.x, 0.f);
        acc.y += fmaxf(v.y + t.y, 0.f);
        acc.z += fmaxf(v.z + t.z, 0.f);
        acc.w += fmaxf(v.w + t.w, 0.f);
    }
    reinterpret_cast<uint2*>(g_z)[(size_t)n * 32 + l] = f4h(acc);
}

// ---------------- tab[r][:] = los_table[r] @ ew + eb --------------------------
__global__ void table_k(const float* __restrict__ lt, const float* __restrict__ ew,
                        const float* __restrict__ eb, float* __restrict__ tab) {
    int r = blockIdx.x, d = threadIdx.x;
    float acc = __ldg(&eb[d]);
#pragma unroll
    for (int j = 0; j < 8; j++)
        acc += __ldg(&lt[r * 8 + j]) * __ldg(&ew[j * DH + d]);
    tab[r * DH + d] = acc;
}

// ---------------- fused MLP, fp16 HMMA (m16n16k16) -----------------------------
// smem: [As | W1s | W2s | params]; W2 preloaded upfront.
// fp32 inter (128x132) overlays As+W1s (dead after GEMM1); W2s preserved.
// Optional fused per-graph column-sum epilogue (atomicAdd into sum_out).
#define HS 136            /* half stride */
#define IS 132            /* float inter stride */
#define AS_BYTES (128*HS*2)          /* 34816 */
#define W1_OFF  AS_BYTES
#define W2_OFF  (2*AS_BYTES)
#define PRM_OFF (3*AS_BYTES)         /* 104448 */
#define MLP_SMEM_BYTES (PRM_OFF + 6*128*4)   /* 107520 */

__device__ __forceinline__ void do_gemm_h(
    const __half* __restrict__ A, const __half* __restrict__ B,
    wmma::fragment<wmma::accumulator, 16, 16, 16, float> (&acc)[8], int wrow)
{
#pragma unroll
    for (int k = 0; k < 8; k++) {
        wmma::fragment<wmma::matrix_a, 16, 16, 16, __half, wmma::row_major> a;
        wmma::load_matrix_sync(a, A + wrow * 16 * HS + k * 16, HS);
#pragma unroll
        for (int j = 0; j < 8; j++) {
            wmma::fragment<wmma::matrix_b, 16, 16, 16, __half, wmma::row_major> b;
            wmma::load_matrix_sync(b, B + k * 16 * HS + j * 16, HS);
            wmma::mma_sync(acc[j], a, b, acc[j]);
        }
    }
}

__global__ __launch_bounds__(256, 2) void mlp_k(
    const __half* __restrict__ A, const __half* __restrict__ W1,
    const float* __restrict__ b1, const float* __restrict__ gam,
    const float* __restrict__ bet, const __half* __restrict__ W2,
    const float* __restrict__ b2, __half* __restrict__ Out,
    float* __restrict__ sum_out, int sum_off)
{
    extern __shared__ char smc[];
    __half* As    = reinterpret_cast<__half*>(smc);
    __half* W1s   = reinterpret_cast<__half*>(smc + W1_OFF);
    __half* W2s   = reinterpret_cast<__half*>(smc + W2_OFF);
    float*  inter = reinterpret_cast<float*>(smc);          // overlays As+W1s
    float*  bs    = reinterpret_cast<float*>(smc + PRM_OFF);
    float*  gs    = bs + 128;
    float*  bes   = gs + 128;
    float*  b2s   = bes + 128;
    float*  mus   = b2s + 128;
    float*  invs  = mus + 128;

    int tid = threadIdx.x;
    int wid = tid >> 5;
    size_t n0 = (size_t)blockIdx.x * 128;

    if (tid < 128) {
        bs[tid]  = __ldg(&b1[tid]);
        gs[tid]  = __ldg(&gam[tid]);
        bes[tid] = __ldg(&bet[tid]);
        b2s[tid] = __ldg(&b2[tid]);
    }

    // load A tile + BOTH weight matrices up front
    {
        const uint4* ap  = reinterpret_cast<const uint4*>(A + n0 * DH);
        const uint4* w1p = reinterpret_cast<const uint4*>(W1);
        const uint4* w2p = reinterpret_cast<const uint4*>(W2);
#pragma unroll
        for (int it = 0; it < 8; it++) {
            int i = tid + it * 256;          // 0..2047
            int r = i >> 4, c8 = (i & 15) * 8;
            *reinterpret_cast<uint4*>(As  + r * HS + c8) = __ldg(ap  + i);
            *reinterpret_cast<uint4*>(W1s + r * HS + c8) = __ldg(w1p + i);
            *reinterpret_cast<uint4*>(W2s + r * HS + c8) = __ldg(w2p + i);
        }
    }
    __syncthreads();

    wmma::fragment<wmma::accumulator, 16, 16, 16, float> acc[8];
#pragma unroll
    for (int j = 0; j < 8; j++) wmma::fill_fragment(acc[j], 0.0f);

    do_gemm_h(As, W1s, acc, wid);
    __syncthreads();                          // all reads of As/W1s done

    // store GEMM1 result to fp32 inter (overlays As+W1s; W2s untouched)
#pragma unroll
    for (int j = 0; j < 8; j++)
        wmma::store_matrix_sync(inter + wid * 16 * IS + j * 16, acc[j], IS, wmma::mem_row_major);
    __syncthreads();

    // LN stats: 2 threads per row
    {
        int row = tid >> 1, hf = tid & 1;
        const float* rp = inter + row * IS + hf * 64;
        const float* bp = bs + hf * 64;
        float s = 0.f, ss = 0.f;
#pragma unroll
        for (int c = 0; c < 64; c++) {
            float xv = rp[c] + bp[c];
            s += xv; ss += xv * xv;
        }
        s  += __shfl_xor_sync(0xffffffffu, s, 1);
        ss += __shfl_xor_sync(0xffffffffu, ss, 1);
        if (hf == 0) {
            float mu = s * (1.0f / 128.0f);
            float var = ss * (1.0f / 128.0f) - mu * mu;
            mus[row] = mu;
            invs[row] = rsqrtf(var + LN_EPSF);
        }
    }
    __syncthreads();

    // apply LN+relu: inter -> regs (half2 packed), then write As
    uint32_t pk[32];
#pragma unroll
    for (int it = 0; it < 32; it++) {
        int i = tid + it * 256;              // 0..8191 (half2 index)
        int r = i >> 6, c2 = i & 63;
        float mu = mus[r], inv = invs[r];
        float x0 = inter[r * IS + 2 * c2]     + bs[2 * c2];
        float x1 = inter[r * IS + 2 * c2 + 1] + bs[2 * c2 + 1];
        float y0 = fmaxf((x0 - mu) * inv * gs[2 * c2]     + bes[2 * c2],     0.f);
        float y1 = fmaxf((x1 - mu) * inv * gs[2 * c2 + 1] + bes[2 * c2 + 1], 0.f);
        __half2 h = __floats2half2_rn(y0, y1);
        pk[it] = *reinterpret_cast<uint32_t*>(&h);
    }
    __syncthreads();                          // all inter reads done
    {
        uint32_t* asu = reinterpret_cast<uint32_t*>(As);
#pragma unroll
        for (int it = 0; it < 32; it++) {
            int i = tid + it * 256;
            int r = i >> 6, c2 = i & 63;
            asu[r * (HS / 2) + c2] = pk[it];
        }
    }
    __syncthreads();

#pragma unroll
    for (int j = 0; j < 8; j++) wmma::fill_fragment(acc[j], 0.0f);

    do_gemm_h(As, W2s, acc, wid);
    __syncthreads();

#pragma unroll
    for (int j = 0; j < 8; j++)
        wmma::store_matrix_sync(inter + wid * 16 * IS + j * 16, acc[j], IS, wmma::mem_row_major);
    __syncthreads();

    // epilogue: + b2, convert to half, write global
    {
        uint32_t* op = reinterpret_cast<uint32_t*>(Out + n0 * DH);
#pragma unroll
        for (int it = 0; it < 32; it++) {
            int i = tid + it * 256;
            int r = i >> 6, c2 = i & 63;
            float x0 = inter[r * IS + 2 * c2]     + b2s[2 * c2];
            float x1 = inter[r * IS + 2 * c2 + 1] + b2s[2 * c2 + 1];
            __half2 h = __floats2half2_rn(x0, x1);
            op[i] = *reinterpret_cast<uint32_t*>(&h);
        }
    }

    // fused per-graph column sums (final layer of each group only)
    if (sum_out != nullptr && tid < 128) {
        int col = tid;
        float b2v = b2s[col];
        float s = 0.f;
#pragma unroll 8
        for (int r = 0; r < 128; r++)
            s += inter[r * IS + col];
        s += 128.0f * b2v;
        int g = (int)(n0 >> 8);              // graph index (2 blocks per graph)
        atomicAdd(&sum_out[g * 256 + sum_off + col], s);
    }
}

// ---------------- launch ------------------------------------------------------
extern "C" void kernel_launch(void* const* d_in, const int* in_sizes, int n_in,
                              void* d_out, int out_size)
{
    const int*   x     = (const int*)d_in[0];
    const int*   ei    = (const int*)d_in[1];
    const int*   los   = (const int*)d_in[2];
    const float* emb   = (const float*)d_in[3];
    const float* lt    = (const float*)d_in[4];
    const float* g1w1  = (const float*)d_in[5];
    const float* g1b1  = (const float*)d_in[6];
    const float* g1g   = (const float*)d_in[7];
    const float* g1be  = (const float*)d_in[8];
    const float* g1w2  = (const float*)d_in[9];
    const float* g1b2  = (const float*)d_in[10];
    const float* g1eps = (const float*)d_in[11];
    const float* g2w1  = (const float*)d_in[12];
    const float* g2b1  = (const float*)d_in[13];
    const float* g2g   = (const float*)d_in[14];
    const float* g2be  = (const float*)d_in[15];
    const float* g2w2  = (const float*)d_in[16];
    const float* g2b2  = (const float*)d_in[17];
    const float* g2eps = (const float*)d_in[18];
    const float* g2ew  = (const float*)d_in[19];
    const float* g2eb  = (const float*)d_in[20];
    float* out = (float*)d_out;

    const int* src = ei;
    const int* dst = ei + EINT;

    void *ph, *pz, *pc, *pw, *pt;
    cudaGetSymbolAddress(&ph, g_h);
    cudaGetSymbolAddress(&pz, g_z);
    cudaGetSymbolAddress(&pc, g_cnt);
    cudaGetSymbolAddress(&pw, g_wh);
    cudaGetSymbolAddress(&pt, g_tab);
    __half* hB = (__half*)ph;
    __half* zB = (__half*)pz;
    __half* wB = (__half*)pw;
    float*  tB = (float*)pt;

    static int smem_set = 0;
    if (!smem_set) {
        cudaFuncSetAttribute(mlp_k, cudaFuncAttributeMaxDynamicSharedMemorySize,
                             MLP_SMEM_BYTES);
        smem_set = 1;
    }

    // zero the output (sums accumulate via atomicAdd)
    cudaMemsetAsync(out, 0, (size_t)out_size * sizeof(float));

    // weights: [g1w1L0, g1w2L0, g1w1L1, g1w2L1, g2w1L0, g2w2L0, g2w1L1, g2w2L1]
    convw_k<<<dim3(64, 8), 256>>>(
        g1w1, g1w2, g1w1 + DH * DH, g1w2 + DH * DH,
        g2w1, g2w2, g2w1 + DH * DH, g2w2 + DH * DH);

    // edge-attr tables for both GINE layers (hoisted off the round path)
    table_k<<<38, DH>>>(lt, g2ew, g2eb, tB);
    table_k<<<38, DH>>>(lt, g2ew + (size_t)8 * DH, g2eb + DH, tB + 38 * DH);

    embed_k<<<(NTOT * 16) / 256, 256>>>(x, emb);

    // CSR build
    cudaMemsetAsync(pc, 0, NTOT * sizeof(int));
    hist_k<<<EINT / 256, 256>>>(dst);
    scanA_k<<<NTOT / 256, 256>>>();
    scanB_k<<<1, 512>>>();
    scanC_k<<<NTOT / 256, 256>>>();
    fill_k<<<EINT / 256, 256>>>(src, dst);

    // ---- GIN layer group 1 ----
    agg1_k<<<(NTOT * 32) / 256, 256>>>(g1eps);
    mlp_k<<<NTOT / 128, 256, MLP_SMEM_BYTES>>>(
        zB, wB + 0 * DH * DH, g1b1, g1g, g1be,
        wB + 1 * DH * DH, g1b2, hB, nullptr, 0);
    agg1_k<<<(NTOT * 32) / 256, 256>>>(g1eps + 1);
    mlp_k<<<NTOT / 128, 256, MLP_SMEM_BYTES>>>(
        zB, wB + 2 * DH * DH, g1b1 + DH, g1g + DH, g1be + DH,
        wB + 3 * DH * DH, g1b2 + DH, hB, out, 0);      // fused ad_dis sums

    // ---- GINE layer group 2 ----
    agg2_k<<<(NTOT * 32) / 256, 256>>>(g2eps, los, tB);
    mlp_k<<<NTOT / 128, 256, MLP_SMEM_BYTES>>>(
        zB, wB + 4 * DH * DH, g2b1, g2g, g2be,
        wB + 5 * DH * DH, g2b2, hB, nullptr, 0);
    agg2_k<<<(NTOT * 32) / 256, 256>>>(g2eps + 1, los, tB + 38 * DH);
    mlp_k<<<NTOT / 128, 256, MLP_SMEM_BYTES>>>(
        zB, wB + 6 * DH * DH, g2b1 + DH, g2g + DH, g2be + DH,
        wB + 7 * DH * DH, g2b2 + DH, hB, out, 128);    // fused x_sum2 sums
}

// round 15
// speedup vs baseline: 1.0593x; 1.0199x over previous
#include <cuda_runtime.h>
#include <cuda_fp16.h>
#include <mma.h>
#include <cstdint>

using namespace nvcuda;

#define NB      256
#define NCOLS   512
#define NNODE   256
#define VOCAB   100
#define DH      128
#define NTOT    (2*NB*NNODE)      /* 131072 nodes */
#define EINT    (NTOT*8)          /* 1048576 edges */
#define MERGED  (NB*NNODE)        /* 65536 */
#define LN_EPSF 1e-5f

// ---------------- scratch (device globals; no allocation allowed) -----------
__device__ __half g_h[(size_t)NTOT * DH];   // node features (fp16)
__device__ __half g_z[(size_t)NTOT * DH];   // (1+eps)*h + agg (fp16)
__device__ float  g_tab[2][38 * DH];        // los_table @ ew + eb (per layer)
__device__ __half g_wh[8][DH * DH];         // fp16-converted weights
__device__ int    g_cnt[NTOT];
__device__ int    g_off[NTOT];
__device__ int    g_cur[NTOT];
__device__ int    g_eid[EINT];
__device__ int    g_part[512];

// ---------------- helpers ------------------------------------------------------
struct F8 { float4 a, b; };

__device__ __forceinline__ float4 h4f(uint2 v) {
    float2 a = __half22float2(*reinterpret_cast<__half2*>(&v.x));
    float2 b = __half22float2(*reinterpret_cast<__half2*>(&v.y));
    return make_float4(a.x, a.y, b.x, b.y);
}
__device__ __forceinline__ uint2 f4h(float4 v) {
    __half2 a = __floats2half2_rn(v.x, v.y);
    __half2 b = __floats2half2_rn(v.z, v.w);
    uint2 r;
    r.x = *reinterpret_cast<uint32_t*>(&a);
    r.y = *reinterpret_cast<uint32_t*>(&b);
    return r;
}
__device__ __forceinline__ uint4 f8u4(F8 v) {
    __half2 h0 = __floats2half2_rn(v.a.x, v.a.y);
    __half2 h1 = __floats2half2_rn(v.a.z, v.a.w);
    __half2 h2 = __floats2half2_rn(v.b.x, v.b.y);
    __half2 h3 = __floats2half2_rn(v.b.z, v.b.w);
    uint4 r;
    r.x = *reinterpret_cast<uint32_t*>(&h0);
    r.y = *reinterpret_cast<uint32_t*>(&h1);
    r.z = *reinterpret_cast<uint32_t*>(&h2);
    r.w = *reinterpret_cast<uint32_t*>(&h3);
    return r;
}

// ---------------- weight pre-convert to fp16 ----------------------------------
__global__ void convw_k(const float* p0, const float* p1, const float* p2,
                        const float* p3, const float* p4, const float* p5,
                        const float* p6, const float* p7) {
    int m = blockIdx.y;
    const float* p = (m == 0) ? p0 : (m == 1) ? p1 : (m == 2) ? p2 : (m == 3) ? p3
                   : (m == 4) ? p4 : (m == 5) ? p5 : (m == 6) ? p6 : p7;
    int i = blockIdx.x * 256 + threadIdx.x;
    g_wh[m][i] = __float2half_rn(__ldg(&p[i]));
}

// ---------------- embedding gather (writes fp16 h, uint4 lanes) ---------------
__global__ void embed_k(const int* __restrict__ x, const float* __restrict__ emb) {
    int tid = blockIdx.x * blockDim.x + threadIdx.x;
    int n = tid >> 4, l = tid & 15;
    if (n >= NTOT) return;
    int c = n & (NCOLS - 1);
    int b = n >> 9;
    int v = __ldg(&x[b * NCOLS + c]);
    const float4* row = reinterpret_cast<const float4*>(emb + ((size_t)c * VOCAB + v) * DH);
    F8 f;
    f.a = __ldg(row + 2 * l);
    f.b = __ldg(row + 2 * l + 1);
    reinterpret_cast<uint4*>(g_h)[(size_t)n * 16 + l] = f8u4(f);
}

// ---------------- CSR build ---------------------------------------------------
__global__ void hist_k(const int* __restrict__ dst) {
    int e = blockIdx.x * 256 + threadIdx.x;
    if (e < EINT) atomicAdd(&g_cnt[__ldg(&dst[e])], 1);
}

__global__ void scanA_k() {
    __shared__ int s[256];
    int t = threadIdx.x;
    int i = blockIdx.x * 256 + t;
    int c = g_cnt[i];
    s[t] = c;
    __syncthreads();
#pragma unroll
    for (int o = 1; o < 256; o <<= 1) {
        int v = (t >= o) ? s[t - o] : 0;
        __syncthreads();
        s[t] += v;
        __syncthreads();
    }
    g_off[i] = s[t];
    if (t == 255) g_part[blockIdx.x] = s[255];
}

// scanC now also computes its own prefix over the 512 partials (scanB removed)
__global__ void scanC_k() {
    __shared__ int wsum[8];
    __shared__ int total;
    int t = threadIdx.x, b = blockIdx.x;
    int loc = 0;
    for (int i = t; i < b; i += 256) loc += g_part[i];
#pragma unroll
    for (int o = 16; o > 0; o >>= 1) loc += __shfl_xor_sync(0xffffffffu, loc, o);
    if ((t & 31) == 0) wsum[t >> 5] = loc;
    __syncthreads();
    if (t == 0) {
        int s = 0;
#pragma unroll
        for (int w = 0; w < 8; w++) s += wsum[w];
        total = s;
    }
    __syncthreads();
    int i = b * 256 + t;
    int off = g_off[i] - g_cnt[i] + total;
    g_off[i] = off;
    g_cur[i] = off;
}

__global__ void fill_k(const int* __restrict__ src, const int* __restrict__ dst) {
    int e = blockIdx.x * 256 + threadIdx.x;
    if (e >= EINT) return;
    int d = __ldg(&dst[e]);
    int p = atomicAdd(&g_cur[d], 1);
    g_eid[p] = __ldg(&src[e]);
}

// ---------------- GIN aggregation (1 node/warp, uint2 lanes, 8-unroll) --------
__global__ void agg1_k(const float* __restrict__ epsp) {
    int tid = blockIdx.x * 256 + threadIdx.x;
    int n = tid >> 5, l = tid & 31;
    float s = 1.0f + __ldg(epsp);
    const uint2* h2 = reinterpret_cast<const uint2*>(g_h);
    float4 a = h4f(h2[(size_t)n * 32 + l]);
    float4 acc = make_float4(a.x * s, a.y * s, a.z * s, a.w * s);
    int off = g_off[n], deg = g_cnt[n];
    int k = 0;
    for (; k + 8 <= deg; k += 8) {
        float4 v[8];
#pragma unroll
        for (int j = 0; j < 8; j++) {
            int e = __ldg(&g_eid[off + k + j]);
            v[j] = h4f(__ldg(&h2[(size_t)e * 32 + l]));
        }
#pragma unroll
        for (int j = 0; j < 8; j++) {
            acc.x += v[j].x; acc.y += v[j].y; acc.z += v[j].z; acc.w += v[j].w;
        }
    }
    for (; k < deg; k++) {
        float4 v = h4f(__ldg(&h2[(size_t)__ldg(&g_eid[off + k]) * 32 + l]));
        acc.x += v.x; acc.y += v.y; acc.z += v.z; acc.w += v.w;
    }
    reinterpret_cast<uint2*>(g_z)[(size_t)n * 32 + l] = f4h(acc);
}

// ---------------- GINE aggregation --------------------------------------------
__global__ void agg2_k(const float* __restrict__ epsp, const int* __restrict__ los,
                       const float* __restrict__ tab) {
    int tid = blockIdx.x * 256 + threadIdx.x;
    int n = tid >> 5, l = tid & 31;
    float s = 1.0f + __ldg(epsp);
    const uint2* h2 = reinterpret_cast<const uint2*>(g_h);
    const float4* t4 = reinterpret_cast<const float4*>(tab);
    float4 c0 = t4[l];
    float4 a = h4f(h2[(size_t)n * 32 + l]);
    float4 acc = make_float4(a.x * s, a.y * s, a.z * s, a.w * s);
    int off = g_off[n], deg = g_cnt[n];
    int k = 0;
    for (; k + 8 <= deg; k += 8) {
        float4 v[8];
#pragma unroll
        for (int j = 0; j < 8; j++) {
            int e = __ldg(&g_eid[off + k + j]);
            v[j] = h4f(__ldg(&h2[(size_t)e * 32 + l]));
        }
#pragma unroll
        for (int j = 0; j < 8; j++) {
            acc.x += fmaxf(v[j].x + c0.x, 0.f);
            acc.y += fmaxf(v[j].y + c0.y, 0.f);
            acc.z += fmaxf(v[j].z + c0.z, 0.f);
            acc.w += fmaxf(v[j].w + c0.w, 0.f);
        }
    }
    for (; k < deg; k++) {
        float4 v = h4f(__ldg(&h2[(size_t)__ldg(&g_eid[off + k]) * 32 + l]));
        acc.x += fmaxf(v.x + c0.x, 0.f);
        acc.y += fmaxf(v.y + c0.y, 0.f);
        acc.z += fmaxf(v.z + c0.z, 0.f);
        acc.w += fmaxf(v.w + c0.w, 0.f);
    }
    if (n >= MERGED) {
        int m = n - MERGED;
        int lo = __ldg(&los[m >> 8]);
        float4 t = t4[lo * 32 + l];
        float4 v = h4f(h2[(size_t)m * 32 + l]);
        acc.x += fmaxf(v.x + t.x, 0.f);
        acc.y += fmaxf(v.y + t.y, 0.f);
        acc.z += fmaxf(v.z + t.z, 0.f);
        acc.w += fmaxf(v.w + t.w, 0.f);
    }
    reinterpret_cast<uint2*>(g_z)[(size_t)n * 32 + l] = f4h(acc);
}

// ---------------- tab[r][:] = los_table[r] @ ew + eb --------------------------
__global__ void table_k(const float* __restrict__ lt, const float* __restrict__ ew,
                        const float* __restrict__ eb, float* __restrict__ tab) {
    int r = blockIdx.x, d = threadIdx.x;
    float acc = __ldg(&eb[d]);
#pragma unroll
    for (int j = 0; j < 8; j++)
        acc += __ldg(&lt[r * 8 + j]) * __ldg(&ew[j * DH + d]);
    tab[r * DH + d] = acc;
}

// ---------------- fused MLP, fp16 HMMA (m16n16k16) -----------------------------
// smem: [As | W1s | W2s | params]; W2 preloaded upfront.
// fp32 inter (128x132) overlays As+W1s (dead after GEMM1); W2s preserved.
// Optional fused per-graph column-sum epilogue (atomicAdd into sum_out).
#define HS 136            /* half stride */
#define IS 132            /* float inter stride */
#define AS_BYTES (128*HS*2)          /* 34816 */
#define W1_OFF  AS_BYTES
#define W2_OFF  (2*AS_BYTES)
#define PRM_OFF (3*AS_BYTES)         /* 104448 */
#define MLP_SMEM_BYTES (PRM_OFF + 6*128*4)   /* 107520 */

__device__ __forceinline__ void do_gemm_h(
    const __half* __restrict__ A, const __half* __restrict__ B,
    wmma::fragment<wmma::accumulator, 16, 16, 16, float> (&acc)[8], int wrow)
{
#pragma unroll
    for (int k = 0; k < 8; k++) {
        wmma::fragment<wmma::matrix_a, 16, 16, 16, __half, wmma::row_major> a;
        wmma::load_matrix_sync(a, A + wrow * 16 * HS + k * 16, HS);
#pragma unroll
        for (int j = 0; j < 8; j++) {
            wmma::fragment<wmma::matrix_b, 16, 16, 16, __half, wmma::row_major> b;
            wmma::load_matrix_sync(b, B + k * 16 * HS + j * 16, HS);
            wmma::mma_sync(acc[j], a, b, acc[j]);
        }
    }
}

__global__ __launch_bounds__(256, 2) void mlp_k(
    const __half* __restrict__ A, const __half* __restrict__ W1,
    const float* __restrict__ b1, const float* __restrict__ gam,
    const float* __restrict__ bet, const __half* __restrict__ W2,
    const float* __restrict__ b2, __half* __restrict__ Out,
    float* __restrict__ sum_out, int sum_off)
{
    extern __shared__ char smc[];
    __half* As    = reinterpret_cast<__half*>(smc);
    __half* W1s   = reinterpret_cast<__half*>(smc + W1_OFF);
    __half* W2s   = reinterpret_cast<__half*>(smc + W2_OFF);
    float*  inter = reinterpret_cast<float*>(smc);          // overlays As+W1s
    float*  bs    = reinterpret_cast<float*>(smc + PRM_OFF);
    float*  gs    = bs + 128;
    float*  bes   = gs + 128;
    float*  b2s   = bes + 128;
    float*  mus   = b2s + 128;
    float*  invs  = mus + 128;

    int tid = threadIdx.x;
    int wid = tid >> 5;
    size_t n0 = (size_t)blockIdx.x * 128;

    if (tid < 128) {
        bs[tid]  = __ldg(&b1[tid]);
        gs[tid]  = __ldg(&gam[tid]);
        bes[tid] = __ldg(&bet[tid]);
        b2s[tid] = __ldg(&b2[tid]);
    }

    // load A tile + BOTH weight matrices up front
    {
        const uint4* ap  = reinterpret_cast<const uint4*>(A + n0 * DH);
        const uint4* w1p = reinterpret_cast<const uint4*>(W1);
        const uint4* w2p = reinterpret_cast<const uint4*>(W2);
#pragma unroll
        for (int it = 0; it < 8; it++) {
            int i = tid + it * 256;          // 0..2047
            int r = i >> 4, c8 = (i & 15) * 8;
            *reinterpret_cast<uint4*>(As  + r * HS + c8) = __ldg(ap  + i);
            *reinterpret_cast<uint4*>(W1s + r * HS + c8) = __ldg(w1p + i);
            *reinterpret_cast<uint4*>(W2s + r * HS + c8) = __ldg(w2p + i);
        }
    }
    __syncthreads();

    wmma::fragment<wmma::accumulator, 16, 16, 16, float> acc[8];
#pragma unroll
    for (int j = 0; j < 8; j++) wmma::fill_fragment(acc[j], 0.0f);

    do_gemm_h(As, W1s, acc, wid);
    __syncthreads();                          // all reads of As/W1s done

    // store GEMM1 result to fp32 inter (overlays As+W1s; W2s untouched)
#pragma unroll
    for (int j = 0; j < 8; j++)
        wmma::store_matrix_sync(inter + wid * 16 * IS + j * 16, acc[j], IS, wmma::mem_row_major);
    __syncthreads();

    // LN stats: 2 threads per row
    {
        int row = tid >> 1, hf = tid & 1;
        const float* rp = inter + row * IS + hf * 64;
        const float* bp = bs + hf * 64;
        float s = 0.f, ss = 0.f;
#pragma unroll
        for (int c = 0; c < 64; c++) {
            float xv = rp[c] + bp[c];
            s += xv; ss += xv * xv;
        }
        s  += __shfl_xor_sync(0xffffffffu, s, 1);
        ss += __shfl_xor_sync(0xffffffffu, ss, 1);
        if (hf == 0) {
            float mu = s * (1.0f / 128.0f);
            float var = ss * (1.0f / 128.0f) - mu * mu;
            mus[row] = mu;
            invs[row] = rsqrtf(var + LN_EPSF);
        }
    }
    __syncthreads();

    // apply LN+relu: inter -> regs (half2 packed), then write As
    uint32_t pk[32];
#pragma unroll
    for (int it = 0; it < 32; it++) {
        int i = tid + it * 256;              // 0..8191 (half2 index)
        int r = i >> 6, c2 = i & 63;
        float mu = mus[r], inv = invs[r];
        float x0 = inter[r * IS + 2 * c2]     + bs[2 * c2];
        float x1 = inter[r * IS + 2 * c2 + 1] + bs[2 * c2 + 1];
        float y0 = fmaxf((x0 - mu) * inv * gs[2 * c2]     + bes[2 * c2],     0.f);
        float y1 = fmaxf((x1 - mu) * inv * gs[2 * c2 + 1] + bes[2 * c2 + 1], 0.f);
        __half2 h = __floats2half2_rn(y0, y1);
        pk[it] = *reinterpret_cast<uint32_t*>(&h);
    }
    __syncthreads();                          // all inter reads done
    {
        uint32_t* asu = reinterpret_cast<uint32_t*>(As);
#pragma unroll
        for (int it = 0; it < 32; it++) {
            int i = tid + it * 256;
            int r = i >> 6, c2 = i & 63;
            asu[r * (HS / 2) + c2] = pk[it];
        }
    }
    __syncthreads();

#pragma unroll
    for (int j = 0; j < 8; j++) wmma::fill_fragment(acc[j], 0.0f);

    do_gemm_h(As, W2s, acc, wid);
    __syncthreads();

#pragma unroll
    for (int j = 0; j < 8; j++)
        wmma::store_matrix_sync(inter + wid * 16 * IS + j * 16, acc[j], IS, wmma::mem_row_major);
    __syncthreads();

    // epilogue: + b2, convert to half, write global
    {
        uint32_t* op = reinterpret_cast<uint32_t*>(Out + n0 * DH);
#pragma unroll
        for (int it = 0; it < 32; it++) {
            int i = tid + it * 256;
            int r = i >> 6, c2 = i & 63;
            float x0 = inter[r * IS + 2 * c2]     + b2s[2 * c2];
            float x1 = inter[r * IS + 2 * c2 + 1] + b2s[2 * c2 + 1];
            __half2 h = __floats2half2_rn(x0, x1);
            op[i] = *reinterpret_cast<uint32_t*>(&h);
        }
    }

    // fused per-graph column sums (final layer of each group only)
    if (sum_out != nullptr && tid < 128) {
        int col = tid;
        float b2v = b2s[col];
        float s = 0.f;
#pragma unroll 8
        for (int r = 0; r < 128; r++)
            s += inter[r * IS + col];
        s += 128.0f * b2v;
        int g = (int)(n0 >> 8);              // graph index (2 blocks per graph)
        atomicAdd(&sum_out[g * 256 + sum_off + col], s);
    }
}

// ---------------- launch ------------------------------------------------------
extern "C" void kernel_launch(void* const* d_in, const int* in_sizes, int n_in,
                              void* d_out, int out_size)
{
    const int*   x     = (const int*)d_in[0];
    const int*   ei    = (const int*)d_in[1];
    const int*   los   = (const int*)d_in[2];
    const float* emb   = (const float*)d_in[3];
    const float* lt    = (const float*)d_in[4];
    const float* g1w1  = (const float*)d_in[5];
    const float* g1b1  = (const float*)d_in[6];
    const float* g1g   = (const float*)d_in[7];
    const float* g1be  = (const float*)d_in[8];
    const float* g1w2  = (const float*)d_in[9];
    const float* g1b2  = (const float*)d_in[10];
    const float* g1eps = (const float*)d_in[11];
    const float* g2w1  = (const float*)d_in[12];
    const float* g2b1  = (const float*)d_in[13];
    const float* g2g   = (const float*)d_in[14];
    const float* g2be  = (const float*)d_in[15];
    const float* g2w2  = (const float*)d_in[16];
    const float* g2b2  = (const float*)d_in[17];
    const float* g2eps = (const float*)d_in[18];
    const float* g2ew  = (const float*)d_in[19];
    const float* g2eb  = (const float*)d_in[20];
    float* out = (float*)d_out;

    const int* src = ei;
    const int* dst = ei + EINT;

    void *ph, *pz, *pc, *pw, *pt;
    cudaGetSymbolAddress(&ph, g_h);
    cudaGetSymbolAddress(&pz, g_z);
    cudaGetSymbolAddress(&pc, g_cnt);
    cudaGetSymbolAddress(&pw, g_wh);
    cudaGetSymbolAddress(&pt, g_tab);
    __half* hB = (__half*)ph;
    __half* zB = (__half*)pz;
    __half* wB = (__half*)pw;
    float*  tB = (float*)pt;

    static int init_done = 0;
    static cudaStream_t s2;
    static cudaEvent_t evFork, evJoin;
    if (!init_done) {
        cudaFuncSetAttribute(mlp_k, cudaFuncAttributeMaxDynamicSharedMemorySize,
                             MLP_SMEM_BYTES);
        cudaStreamCreateWithFlags(&s2, cudaStreamNonBlocking);
        cudaEventCreateWithFlags(&evFork, cudaEventDisableTiming);
        cudaEventCreateWithFlags(&evJoin, cudaEventDisableTiming);
        init_done = 1;
    }

    // zero the output (sums accumulate via atomicAdd)
    cudaMemsetAsync(out, 0, (size_t)out_size * sizeof(float));

    // ---- fork: CSR build on s2, front-end on default stream ----
    cudaEventRecord(evFork, 0);
    cudaStreamWaitEvent(s2, evFork, 0);

    cudaMemsetAsync(pc, 0, NTOT * sizeof(int), s2);
    hist_k<<<EINT / 256, 256, 0, s2>>>(dst);
    scanA_k<<<NTOT / 256, 256, 0, s2>>>();
    scanC_k<<<NTOT / 256, 256, 0, s2>>>();
    fill_k<<<EINT / 256, 256, 0, s2>>>(src, dst);
    cudaEventRecord(evJoin, s2);

    // front-end (default stream)
    convw_k<<<dim3(64, 8), 256>>>(
        g1w1, g1w2, g1w1 + DH * DH, g1w2 + DH * DH,
        g2w1, g2w2, g2w1 + DH * DH, g2w2 + DH * DH);
    table_k<<<38, DH>>>(lt, g2ew, g2eb, tB);
    table_k<<<38, DH>>>(lt, g2ew + (size_t)8 * DH, g2eb + DH, tB + 38 * DH);
    embed_k<<<(NTOT * 16) / 256, 256>>>(x, emb);

    // join: aggregation needs both CSR and embeddings
    cudaStreamWaitEvent(0, evJoin, 0);

    // ---- GIN layer group 1 ----
    agg1_k<<<(NTOT * 32) / 256, 256>>>(g1eps);
    mlp_k<<<NTOT / 128, 256, MLP_SMEM_BYTES>>>(
        zB, wB + 0 * DH * DH, g1b1, g1g, g1be,
        wB + 1 * DH * DH, g1b2, hB, nullptr, 0);
    agg1_k<<<(NTOT * 32) / 256, 256>>>(g1eps + 1);
    mlp_k<<<NTOT / 128, 256, MLP_SMEM_BYTES>>>(
        zB, wB + 2 * DH * DH, g1b1 + DH, g1g + DH, g1be + DH,
        wB + 3 * DH * DH, g1b2 + DH, hB, out, 0);      // fused ad_dis sums

    // ---- GINE layer group 2 ----
    agg2_k<<<(NTOT * 32) / 256, 256>>>(g2eps, los, tB);
    mlp_k<<<NTOT / 128, 256, MLP_SMEM_BYTES>>>(
        zB, wB + 4 * DH * DH, g2b1, g2g, g2be,
        wB + 5 * DH * DH, g2b2, hB, nullptr, 0);
    agg2_k<<<(NTOT * 32) / 256, 256>>>(g2eps + 1, los, tB + 38 * DH);
    mlp_k<<<NTOT / 128, 256, MLP_SMEM_BYTES>>>(
        zB, wB + 6 * DH * DH, g2b1 + DH, g2g + DH, g2be + DH,
        wB + 7 * DH * DH, g2b2 + DH, hB, out, 128);    // fused x_sum2 sums
}